// round 12
// baseline (speedup 1.0000x reference)
#include <cuda_runtime.h>
#include <math.h>

#define T_LEN 256
#define BATCH 64
#define INDIM 512
#define HDIM  1024
#define M_TOT (T_LEN * BATCH)   /* 16384 */
#define G4    (4 * HDIM)        /* 4096  */
#define NBLK_LSTM 128

/* ------------------------------------------------------------------ */
__device__ float    g_xproj [M_TOT * G4];
__device__ float    g_hs    [M_TOT * HDIM];
__device__ float    g_logits[M_TOT * INDIM];
__device__ unsigned g_flag  [T_LEN][8];     /* per-(step,chunk) arrival */
__device__ unsigned g_epoch;                /* completed-launch count   */
__device__ unsigned g_bar;                  /* final ticket barrier     */

/* ------------------------------------------------------------------ */
__device__ __forceinline__ float sigmoidf_(float x) {
    return 1.0f / (1.0f + expf(-x));
}
__device__ __forceinline__ void cp_async16(float* smem_dst, const float* gsrc) {
    unsigned sa = (unsigned)__cvta_generic_to_shared(smem_dst);
    asm volatile("cp.async.cg.shared.global [%0], [%1], 16;\n" :: "r"(sa), "l"(gsrc));
}
__device__ __forceinline__ void cp_commit() {
    asm volatile("cp.async.commit_group;\n" ::: "memory");
}
__device__ __forceinline__ void cp_wait0() {
    asm volatile("cp.async.wait_group 0;\n" ::: "memory");
}
__device__ __forceinline__ void cp_wait1() {
    asm volatile("cp.async.wait_group 1;\n" ::: "memory");
}

/* tf32 mma m16n8k8 (fp32 accum) */
__device__ __forceinline__ void mma_tf32(float* c, const unsigned* a,
                                         const unsigned* b) {
    asm volatile(
        "mma.sync.aligned.m16n8k8.row.col.f32.tf32.tf32.f32 "
        "{%0,%1,%2,%3}, {%4,%5,%6,%7}, {%8,%9}, {%0,%1,%2,%3};"
        : "+f"(c[0]), "+f"(c[1]), "+f"(c[2]), "+f"(c[3])
        : "r"(a[0]), "r"(a[1]), "r"(a[2]), "r"(a[3]), "r"(b[0]), "r"(b[1]));
}
__device__ __forceinline__ unsigned fbits(float x) { return __float_as_uint(x); }

/* ------------------------------------------------------------------ */
/* tf32 GEMM (unchanged from Round 7)                                 */
/* ------------------------------------------------------------------ */
#define GST 36

template <int KDIM, int NDIM, int MODE>
__global__ __launch_bounds__(256, 2)
void gemm_tf32(const float* __restrict__ Aext,
               const float* __restrict__ B,
               const float* __restrict__ bias,
               const float* __restrict__ img) {
    extern __shared__ __align__(16) float sm[];
    const float* __restrict__ Ap = (MODE == 0) ? Aext : g_hs;
    float* __restrict__       Cp = (MODE == 0) ? g_xproj : g_logits;

    const int bm   = blockIdx.y * 128;
    const int bn   = blockIdx.x * 128;
    const int tid  = threadIdx.x;
    const int lane = tid & 31;
    const int warp = tid >> 5;
    const int wm   = warp & 1;
    const int wn   = warp >> 1;

    float acc[4][4][4];
#pragma unroll
    for (int i = 0; i < 4; i++)
#pragma unroll
        for (int j = 0; j < 4; j++)
#pragma unroll
            for (int v = 0; v < 4; v++) acc[i][j][v] = 0.0f;

    const int NCH = KDIM / 32;

    {
        float* As = sm;
        float* Bs = sm + 128 * GST;
#pragma unroll
        for (int i = 0; i < 4; i++) {
            const int idx = tid + i * 256;
            const int row = idx >> 3, q = idx & 7;
            cp_async16(&As[row * GST + q * 4], Ap + (size_t)(bm + row) * KDIM + q * 4);
            cp_async16(&Bs[row * GST + q * 4], B  + (size_t)(bn + row) * KDIM + q * 4);
        }
        cp_commit();
    }

    for (int ck = 0; ck < NCH; ck++) {
        const int buf = ck & 1;
        if (ck + 1 < NCH) {
            float* As = sm + ((ck + 1) & 1) * (256 * GST);
            float* Bs = As + 128 * GST;
            const int kt = (ck + 1) * 32;
#pragma unroll
            for (int i = 0; i < 4; i++) {
                const int idx = tid + i * 256;
                const int row = idx >> 3, q = idx & 7;
                cp_async16(&As[row * GST + q * 4],
                           Ap + (size_t)(bm + row) * KDIM + kt + q * 4);
                cp_async16(&Bs[row * GST + q * 4],
                           B + (size_t)(bn + row) * KDIM + kt + q * 4);
            }
            cp_commit();
            cp_wait1();
        } else {
            cp_wait0();
        }
        __syncthreads();

        const float* As = sm + buf * (256 * GST) + (wm * 64) * GST;
        const float* Bs = sm + buf * (256 * GST) + 128 * GST + (wn * 32) * GST;
#pragma unroll
        for (int ks = 0; ks < 4; ks++) {
            const int col = ks * 8 + (lane & 3);
            unsigned af[4][4];
#pragma unroll
            for (int mt = 0; mt < 4; mt++) {
                const int row = mt * 16 + (lane >> 2);
                af[mt][0] = fbits(As[row * GST + col]);
                af[mt][1] = fbits(As[(row + 8) * GST + col]);
                af[mt][2] = fbits(As[row * GST + col + 4]);
                af[mt][3] = fbits(As[(row + 8) * GST + col + 4]);
            }
#pragma unroll
            for (int nt = 0; nt < 4; nt++) {
                const int nr = nt * 8 + (lane >> 2);
                unsigned bf[2];
                bf[0] = fbits(Bs[nr * GST + col]);
                bf[1] = fbits(Bs[nr * GST + col + 4]);
#pragma unroll
                for (int mt = 0; mt < 4; mt++)
                    mma_tf32(acc[mt][nt], af[mt], bf);
            }
        }
        __syncthreads();
    }

#pragma unroll
    for (int mt = 0; mt < 4; mt++) {
#pragma unroll
        for (int nt = 0; nt < 4; nt++) {
            const int m = bm + wm * 64 + mt * 16 + (lane >> 2);
            const int n = bn + wn * 32 + nt * 8 + 2 * (lane & 3);
            const float2 bv = *(const float2*)&bias[n];
            float o0 = acc[mt][nt][0] + bv.x;
            float o1 = acc[mt][nt][1] + bv.y;
            float o2 = acc[mt][nt][2] + bv.x;
            float o3 = acc[mt][nt][3] + bv.y;
            if (MODE == 0) {
                if (m < BATCH) {
                    o0 += img[m * HDIM + (n & (HDIM - 1))];
                    o1 += img[m * HDIM + ((n + 1) & (HDIM - 1))];
                }
                if (m + 8 < BATCH) {
                    o2 += img[(m + 8) * HDIM + (n & (HDIM - 1))];
                    o3 += img[(m + 8) * HDIM + ((n + 1) & (HDIM - 1))];
                }
            }
            *(float2*)(Cp + (size_t)m * NDIM + n)       = make_float2(o0, o1);
            *(float2*)(Cp + (size_t)(m + 8) * NDIM + n) = make_float2(o2, o3);
        }
    }
}

/* ------------------------------------------------------------------ */
/* Persistent LSTM — tf32 mma engine + per-chunk producer flags.      */
/* CTA b owns units [8b, 8b+8). Chunk ch (k in [128ch,128ch+128)) is  */
/* produced by CTAs 16ch..16ch+15. Consumers wait flag[t-1][ch] and   */
/* pipeline staging/compute chunk-by-chunk. Replay-safe via g_epoch.  */
/* ------------------------------------------------------------------ */
#define WST 1028
#define HST 132
#define PST 36
#define HS_OFF  (32 * WST)
#define PRE_OFF (HS_OFF + 2 * 64 * HST)
#define PRE_SZ  (64 * PST)

__device__ __forceinline__ void wait_flag(const unsigned* p, unsigned tgt) {
    if (threadIdx.x == 0) {
        while (*(volatile const unsigned*)p < tgt) { }
        __threadfence();
    }
    __syncthreads();
}

__global__ __launch_bounds__(256, 1)
void lstm_kernel(const float* __restrict__ Whh,
                 const float* __restrict__ bhh) {
    extern __shared__ __align__(16) float sm[];
    float* Ws  = sm;
    float* hs0 = sm + HS_OFF;
    float* pre = sm + PRE_OFF;

    const int tid  = threadIdx.x;
    const int lane = tid & 31;
    const int warp = tid >> 5;
    const int mg   = warp & 3;
    const int kg   = warp >> 2;
    const int j0   = blockIdx.x * 8;
    const int gid  = blockIdx.x >> 4;     /* producer flag group */

    /* epoch base: all flag slots equal 16*epoch at launch start */
    const unsigned epoch   = *(volatile unsigned*)&g_epoch;
    const unsigned ftarget = epoch * 16u + 16u;

    const int gb  = tid >> 2;
    const int gu0 = tid & 3;
    const int gu1 = gu0 + 4;

    const int sb = tid & 63;
    const int sq = tid >> 6;

    for (int idx = tid; idx < 32 * 256; idx += 256) {
        const int r = idx & 31, k4 = idx >> 5;
        const int u = r >> 2, g = r & 3;
        float4 w = *(const float4*)&Whh[(size_t)(g * HDIM + j0 + u) * HDIM + k4 * 4];
        *(float4*)&Ws[r * WST + k4 * 4] = w;
    }
    float bh0[4], bh1[4];
#pragma unroll
    for (int g = 0; g < 4; g++) {
        bh0[g] = bhh[g * HDIM + j0 + gu0];
        bh1[g] = bhh[g * HDIM + j0 + gu1];
    }
    float c0 = 0.0f, c1 = 0.0f;
    __syncthreads();

    for (int t = 0; t < T_LEN; t++) {
        float xp0[4], xp1[4];
        {
            const float* xb = g_xproj + (size_t)t * BATCH * G4 + (size_t)gb * G4 + j0;
#pragma unroll
            for (int g = 0; g < 4; g++) {
                xp0[g] = __ldg(xb + g * HDIM + gu0);
                xp1[g] = __ldg(xb + g * HDIM + gu1);
            }
        }

        if (t > 0) {
            const float* __restrict__ hp = g_hs + (size_t)(t - 1) * BATCH * HDIM;

            /* stage chunk 0 once its 16 producers are done */
            wait_flag(&g_flag[t - 1][0], ftarget);
#pragma unroll
            for (int i = 0; i < 8; i++) {
                const int k4 = sq + 4 * i;
                cp_async16(&hs0[sb * HST + k4 * 4], hp + (size_t)sb * HDIM + k4 * 4);
            }
            cp_commit();

            float acc[4][4];
#pragma unroll
            for (int nt = 0; nt < 4; nt++)
#pragma unroll
                for (int v = 0; v < 4; v++) acc[nt][v] = 0.0f;

#pragma unroll 1
            for (int ch = 0; ch < 8; ch++) {
                if (ch < 7) {
                    wait_flag(&g_flag[t - 1][ch + 1], ftarget);
                    float* dst = hs0 + ((ch + 1) & 1) * (64 * HST);
#pragma unroll
                    for (int i = 0; i < 8; i++) {
                        const int k4 = sq + 4 * i;
                        cp_async16(&dst[sb * HST + k4 * 4],
                                   hp + (size_t)sb * HDIM + (ch + 1) * 128 + k4 * 4);
                    }
                    cp_commit();
                    cp_wait1();
                } else {
                    cp_wait0();
                }
                __syncthreads();

                const float* Ab = hs0 + (ch & 1) * (64 * HST) + (mg * 16) * HST
                                  + kg * 64;
                const float* Wb = Ws + ch * 128 + kg * 64;
#pragma unroll
                for (int ks = 0; ks < 8; ks++) {
                    const int col = ks * 8 + (lane & 3);
                    unsigned af[4];
                    {
                        const float* a = Ab + (lane >> 2) * HST + col;
                        af[0] = fbits(a[0]);
                        af[1] = fbits(a[8 * HST]);
                        af[2] = fbits(a[4]);
                        af[3] = fbits(a[8 * HST + 4]);
                    }
#pragma unroll
                    for (int nt = 0; nt < 4; nt++) {
                        const float* b = Wb + (nt * 8 + (lane >> 2)) * WST + col;
                        unsigned bf[2];
                        bf[0] = fbits(b[0]);
                        bf[1] = fbits(b[4]);
                        mma_tf32(acc[nt], af, bf);
                    }
                }
                __syncthreads();
            }

            {
                float* pg = pre + kg * PRE_SZ;
#pragma unroll
                for (int nt = 0; nt < 4; nt++) {
                    const int m = mg * 16 + (lane >> 2);
                    const int n = nt * 8 + 2 * (lane & 3);
                    *(float2*)&pg[m * PST + n]       = make_float2(acc[nt][0], acc[nt][1]);
                    *(float2*)&pg[(m + 8) * PST + n] = make_float2(acc[nt][2], acc[nt][3]);
                }
            }
        }
        __syncthreads();

        /* gate math: 2 cells per thread */
        {
            float s0[4], s1[4];
            if (t > 0) {
                float4 p00 = *(const float4*)&pre[gb * PST + gu0 * 4];
                float4 p01 = *(const float4*)&pre[PRE_SZ + gb * PST + gu0 * 4];
                float4 p10 = *(const float4*)&pre[gb * PST + gu1 * 4];
                float4 p11 = *(const float4*)&pre[PRE_SZ + gb * PST + gu1 * 4];
                s0[0] = p00.x + p01.x; s0[1] = p00.y + p01.y;
                s0[2] = p00.z + p01.z; s0[3] = p00.w + p01.w;
                s1[0] = p10.x + p11.x; s1[1] = p10.y + p11.y;
                s1[2] = p10.z + p11.z; s1[3] = p10.w + p11.w;
            } else {
#pragma unroll
                for (int g = 0; g < 4; g++) { s0[g] = 0.0f; s1[g] = 0.0f; }
            }
#pragma unroll
            for (int g = 0; g < 4; g++) {
                s0[g] += xp0[g] + bh0[g];
                s1[g] += xp1[g] + bh1[g];
            }
            {
                float ig = sigmoidf_(s0[0]), fg = sigmoidf_(s0[1]);
                float gg = tanhf(s0[2]),     og = sigmoidf_(s0[3]);
                c0 = fg * c0 + ig * gg;
                g_hs[(size_t)t * BATCH * HDIM + (size_t)gb * HDIM + j0 + gu0] =
                    og * tanhf(c0);
            }
            {
                float ig = sigmoidf_(s1[0]), fg = sigmoidf_(s1[1]);
                float gg = tanhf(s1[2]),     og = sigmoidf_(s1[3]);
                c1 = fg * c1 + ig * gg;
                g_hs[(size_t)t * BATCH * HDIM + (size_t)gb * HDIM + j0 + gu1] =
                    og * tanhf(c1);
            }
        }

        /* publish: this CTA's slice of h(t) is globally visible */
        __syncthreads();
        if (tid == 0) {
            __threadfence();
            atomicAdd(&g_flag[t][gid], 1u);
        }
    }

    /* final ticket barrier (self-contained, replay-safe), then epoch++ */
    if (tid == 0) {
        __threadfence();
        unsigned ticket = atomicAdd(&g_bar, 1u);
        unsigned target = (ticket / NBLK_LSTM + 1u) * NBLK_LSTM;
        while (*((volatile unsigned*)&g_bar) < target) { }
    }
    __syncthreads();
    if (blockIdx.x == 0 && tid == 0) {
        __threadfence();
        *(volatile unsigned*)&g_epoch = epoch + 1u;
    }
}

/* ------------------------------------------------------------------ */
__global__ __launch_bounds__(256)
void logsoftmax_kernel(float* __restrict__ out) {
    __shared__ float red[8];
    const int row = blockIdx.x;
    const int tid = threadIdx.x;
    const float* x = g_logits + (size_t)row * INDIM;
    float v0 = x[tid];
    float v1 = x[tid + 256];

    float m = fmaxf(v0, v1);
#pragma unroll
    for (int o = 16; o; o >>= 1) m = fmaxf(m, __shfl_xor_sync(0xffffffffu, m, o));
    if ((tid & 31) == 0) red[tid >> 5] = m;
    __syncthreads();
    float M = fmaxf(fmaxf(fmaxf(red[0], red[1]), fmaxf(red[2], red[3])),
                    fmaxf(fmaxf(red[4], red[5]), fmaxf(red[6], red[7])));
    __syncthreads();

    float s = expf(v0 - M) + expf(v1 - M);
#pragma unroll
    for (int o = 16; o; o >>= 1) s += __shfl_xor_sync(0xffffffffu, s, o);
    if ((tid & 31) == 0) red[tid >> 5] = s;
    __syncthreads();
    float S = (red[0] + red[1]) + (red[2] + red[3]) +
              (red[4] + red[5]) + (red[6] + red[7]);
    float lse = M + logf(S);

    out[(size_t)row * INDIM + tid]       = v0 - lse;
    out[(size_t)row * INDIM + tid + 256] = v1 - lse;
}

/* ------------------------------------------------------------------ */
extern "C" void kernel_launch(void* const* d_in, const int* in_sizes, int n_in,
                              void* d_out, int out_size) {
    const float* inp  = (const float*)d_in[0];
    const float* img  = (const float*)d_in[1];
    const float* Wxh  = (const float*)d_in[2];
    const float* bxh  = (const float*)d_in[3];
    const float* Whh  = (const float*)d_in[4];
    const float* bhh  = (const float*)d_in[5];
    const float* Wout = (const float*)d_in[6];
    const float* bout = (const float*)d_in[7];
    float* out = (float*)d_out;

    const int gemm_smem = 2 * 2 * 128 * GST * (int)sizeof(float);
    const int lstm_smem = (PRE_OFF + 2 * PRE_SZ) * (int)sizeof(float);

    cudaFuncSetAttribute(gemm_tf32<INDIM, G4, 0>,
                         cudaFuncAttributeMaxDynamicSharedMemorySize, gemm_smem);
    cudaFuncSetAttribute(gemm_tf32<HDIM, INDIM, 1>,
                         cudaFuncAttributeMaxDynamicSharedMemorySize, gemm_smem);
    cudaFuncSetAttribute(lstm_kernel,
                         cudaFuncAttributeMaxDynamicSharedMemorySize, lstm_smem);

    gemm_tf32<INDIM, G4, 0><<<dim3(G4 / 128, M_TOT / 128), 256, gemm_smem>>>
        (inp, Wxh, bxh, img);
    lstm_kernel<<<NBLK_LSTM, 256, lstm_smem>>>(Whh, bhh);
    gemm_tf32<HDIM, INDIM, 1><<<dim3(INDIM / 128, M_TOT / 128), 256, gemm_smem>>>
        (nullptr, Wout, bout, nullptr);
    logsoftmax_kernel<<<M_TOT, 256>>>(out);
}

// round 13
// speedup vs baseline: 1.4456x; 1.4456x over previous
#include <cuda_runtime.h>
#include <cuda_bf16.h>
#include <math.h>

#define T_LEN 256
#define BATCH 64
#define INDIM 512
#define HDIM  1024
#define M_TOT (T_LEN * BATCH)   /* 16384 */
#define G4    (4 * HDIM)        /* 4096  */
#define NBLK_LSTM 128

/* ------------------------------------------------------------------ */
__device__ float    g_xproj [M_TOT * G4];
__device__ __align__(256) unsigned g_hs_bf[M_TOT * HDIM / 2]; /* bf16 h */
__device__ float    g_hs32  [M_TOT * HDIM];                   /* fp32 h */
__device__ float    g_logits[M_TOT * INDIM];
__device__ unsigned g_arr   [T_LEN][NBLK_LSTM];  /* per-(step,cta) flags */
__device__ unsigned g_epoch;
__device__ unsigned g_bar;

/* ------------------------------------------------------------------ */
__device__ __forceinline__ float sigmoidf_(float x) {
    return 1.0f / (1.0f + expf(-x));
}
__device__ __forceinline__ void cp_async16(float* smem_dst, const float* gsrc) {
    unsigned sa = (unsigned)__cvta_generic_to_shared(smem_dst);
    asm volatile("cp.async.cg.shared.global [%0], [%1], 16;\n" :: "r"(sa), "l"(gsrc));
}
__device__ __forceinline__ void cp_commit() {
    asm volatile("cp.async.commit_group;\n" ::: "memory");
}
__device__ __forceinline__ void cp_wait0() {
    asm volatile("cp.async.wait_group 0;\n" ::: "memory");
}
__device__ __forceinline__ void cp_wait1() {
    asm volatile("cp.async.wait_group 1;\n" ::: "memory");
}

/* tf32 mma m16n8k8 (fp32 accum) — GEMMs */
__device__ __forceinline__ void mma_tf32(float* c, const unsigned* a,
                                         const unsigned* b) {
    asm volatile(
        "mma.sync.aligned.m16n8k8.row.col.f32.tf32.tf32.f32 "
        "{%0,%1,%2,%3}, {%4,%5,%6,%7}, {%8,%9}, {%0,%1,%2,%3};"
        : "+f"(c[0]), "+f"(c[1]), "+f"(c[2]), "+f"(c[3])
        : "r"(a[0]), "r"(a[1]), "r"(a[2]), "r"(a[3]), "r"(b[0]), "r"(b[1]));
}
/* bf16 mma m16n8k16 (fp32 accum) — recurrence */
__device__ __forceinline__ void mma_bf16(float* c, const unsigned* a,
                                         const unsigned* b) {
    asm volatile(
        "mma.sync.aligned.m16n8k16.row.col.f32.bf16.bf16.f32 "
        "{%0,%1,%2,%3}, {%4,%5,%6,%7}, {%8,%9}, {%0,%1,%2,%3};"
        : "+f"(c[0]), "+f"(c[1]), "+f"(c[2]), "+f"(c[3])
        : "r"(a[0]), "r"(a[1]), "r"(a[2]), "r"(a[3]), "r"(b[0]), "r"(b[1]));
}
__device__ __forceinline__ unsigned fbits(float x) { return __float_as_uint(x); }

/* ------------------------------------------------------------------ */
/* tf32 GEMM (unchanged, proven)                                      */
/* ------------------------------------------------------------------ */
#define GST 36

template <int KDIM, int NDIM, int MODE>
__global__ __launch_bounds__(256, 2)
void gemm_tf32(const float* __restrict__ Aext,
               const float* __restrict__ B,
               const float* __restrict__ bias,
               const float* __restrict__ img) {
    extern __shared__ __align__(16) float sm[];
    const float* __restrict__ Ap = (MODE == 0) ? Aext : g_hs32;
    float* __restrict__       Cp = (MODE == 0) ? g_xproj : g_logits;

    const int bm   = blockIdx.y * 128;
    const int bn   = blockIdx.x * 128;
    const int tid  = threadIdx.x;
    const int lane = tid & 31;
    const int warp = tid >> 5;
    const int wm   = warp & 1;
    const int wn   = warp >> 1;

    float acc[4][4][4];
#pragma unroll
    for (int i = 0; i < 4; i++)
#pragma unroll
        for (int j = 0; j < 4; j++)
#pragma unroll
            for (int v = 0; v < 4; v++) acc[i][j][v] = 0.0f;

    const int NCH = KDIM / 32;

    {
        float* As = sm;
        float* Bs = sm + 128 * GST;
#pragma unroll
        for (int i = 0; i < 4; i++) {
            const int idx = tid + i * 256;
            const int row = idx >> 3, q = idx & 7;
            cp_async16(&As[row * GST + q * 4], Ap + (size_t)(bm + row) * KDIM + q * 4);
            cp_async16(&Bs[row * GST + q * 4], B  + (size_t)(bn + row) * KDIM + q * 4);
        }
        cp_commit();
    }

    for (int ck = 0; ck < NCH; ck++) {
        const int buf = ck & 1;
        if (ck + 1 < NCH) {
            float* As = sm + ((ck + 1) & 1) * (256 * GST);
            float* Bs = As + 128 * GST;
            const int kt = (ck + 1) * 32;
#pragma unroll
            for (int i = 0; i < 4; i++) {
                const int idx = tid + i * 256;
                const int row = idx >> 3, q = idx & 7;
                cp_async16(&As[row * GST + q * 4],
                           Ap + (size_t)(bm + row) * KDIM + kt + q * 4);
                cp_async16(&Bs[row * GST + q * 4],
                           B + (size_t)(bn + row) * KDIM + kt + q * 4);
            }
            cp_commit();
            cp_wait1();
        } else {
            cp_wait0();
        }
        __syncthreads();

        const float* As = sm + buf * (256 * GST) + (wm * 64) * GST;
        const float* Bs = sm + buf * (256 * GST) + 128 * GST + (wn * 32) * GST;
#pragma unroll
        for (int ks = 0; ks < 4; ks++) {
            const int col = ks * 8 + (lane & 3);
            unsigned af[4][4];
#pragma unroll
            for (int mt = 0; mt < 4; mt++) {
                const int row = mt * 16 + (lane >> 2);
                af[mt][0] = fbits(As[row * GST + col]);
                af[mt][1] = fbits(As[(row + 8) * GST + col]);
                af[mt][2] = fbits(As[row * GST + col + 4]);
                af[mt][3] = fbits(As[(row + 8) * GST + col + 4]);
            }
#pragma unroll
            for (int nt = 0; nt < 4; nt++) {
                const int nr = nt * 8 + (lane >> 2);
                unsigned bf[2];
                bf[0] = fbits(Bs[nr * GST + col]);
                bf[1] = fbits(Bs[nr * GST + col + 4]);
#pragma unroll
                for (int mt = 0; mt < 4; mt++)
                    mma_tf32(acc[mt][nt], af[mt], bf);
            }
        }
        __syncthreads();
    }

#pragma unroll
    for (int mt = 0; mt < 4; mt++) {
#pragma unroll
        for (int nt = 0; nt < 4; nt++) {
            const int m = bm + wm * 64 + mt * 16 + (lane >> 2);
            const int n = bn + wn * 32 + nt * 8 + 2 * (lane & 3);
            const float2 bv = *(const float2*)&bias[n];
            float o0 = acc[mt][nt][0] + bv.x;
            float o1 = acc[mt][nt][1] + bv.y;
            float o2 = acc[mt][nt][2] + bv.x;
            float o3 = acc[mt][nt][3] + bv.y;
            if (MODE == 0) {
                if (m < BATCH) {
                    o0 += img[m * HDIM + (n & (HDIM - 1))];
                    o1 += img[m * HDIM + ((n + 1) & (HDIM - 1))];
                }
                if (m + 8 < BATCH) {
                    o2 += img[(m + 8) * HDIM + (n & (HDIM - 1))];
                    o3 += img[(m + 8) * HDIM + ((n + 1) & (HDIM - 1))];
                }
            }
            *(float2*)(Cp + (size_t)m * NDIM + n)       = make_float2(o0, o1);
            *(float2*)(Cp + (size_t)(m + 8) * NDIM + n) = make_float2(o2, o3);
        }
    }
}

/* ------------------------------------------------------------------ */
/* Persistent LSTM — bf16 mma engine + atomic-free poll barrier.      */
/* Word-based smem layout (uint = bf16x2):                            */
/*   Ws  [32 r][516 w]   (66 KB)   rows stride 516 = 4 mod 32         */
/*   hs  [2][64 b][132 w](67.5 KB) rows stride 132 = 4 mod 32         */
/*   pre [2][64][36] fp32 (18.4 KB)                                   */
/* Chunk = 256 k (128 words); 4 chunks, double-buffered cp.async.     */
/* ------------------------------------------------------------------ */
#define WSW 516
#define HSW 132
#define PST 36
#define W_WORDS  (32 * WSW)                    /* 16512 */
#define HS_OFF_W (W_WORDS)
#define HCHUNK_W (64 * HSW)                    /* 8448  */
#define PRE_OFF_W (HS_OFF_W + 2 * HCHUNK_W)    /* 33408 */
#define PRE_SZ   (64 * PST)

__global__ __launch_bounds__(256, 1)
void lstm_kernel(const float* __restrict__ Whh,
                 const float* __restrict__ bhh) {
    extern __shared__ __align__(16) unsigned smu[];
    unsigned* Ws  = smu;
    unsigned* hs0 = smu + HS_OFF_W;
    float*    pre = (float*)(smu + PRE_OFF_W);

    const int tid  = threadIdx.x;
    const int lane = tid & 31;
    const int warp = tid >> 5;
    const int mg   = warp & 3;     /* 16-batch slice  */
    const int kg   = warp >> 2;    /* k half          */
    const int j0   = blockIdx.x * 8;
    const int bid  = blockIdx.x;

    const unsigned epoch = *(volatile unsigned*)&g_epoch;
    const unsigned tgt   = epoch + 1u;

    const int gb  = tid >> 2;
    const int gu0 = tid & 3;
    const int gu1 = gu0 + 4;

    const int sb = tid & 63;       /* staging batch row  */
    const int sq = tid >> 6;       /* staging 16B slot   */

    /* stage Whh -> bf16 smem (once): Ws[r][k], r = u*4+g */
    for (int idx = tid; idx < 32 * 256; idx += 256) {
        const int r = idx & 31, k4 = idx >> 5;
        const int u = r >> 2, g = r & 3;
        float4 w = *(const float4*)&Whh[(size_t)(g * HDIM + j0 + u) * HDIM + k4 * 4];
        __nv_bfloat162 lo = __floats2bfloat162_rn(w.x, w.y);
        __nv_bfloat162 hi = __floats2bfloat162_rn(w.z, w.w);
        Ws[r * WSW + k4 * 2]     = reinterpret_cast<unsigned&>(lo);
        Ws[r * WSW + k4 * 2 + 1] = reinterpret_cast<unsigned&>(hi);
    }
    float bh0[4], bh1[4];
#pragma unroll
    for (int g = 0; g < 4; g++) {
        bh0[g] = bhh[g * HDIM + j0 + gu0];
        bh1[g] = bhh[g * HDIM + j0 + gu1];
    }
    float c0 = 0.0f, c1 = 0.0f;
    __syncthreads();

    for (int t = 0; t < T_LEN; t++) {
        /* xproj prefetch (independent of flags; overlaps the wait) */
        float xp0[4], xp1[4];
        {
            const float* xb = g_xproj + (size_t)t * BATCH * G4 + (size_t)gb * G4 + j0;
#pragma unroll
            for (int g = 0; g < 4; g++) {
                xp0[g] = __ldg(xb + g * HDIM + gu0);
                xp1[g] = __ldg(xb + g * HDIM + gu1);
            }
        }

        if (t > 0) {
            /* all-poll-all barrier: thread i<128 watches CTA i's flag */
            if (tid < NBLK_LSTM) {
                while (*(volatile unsigned*)&g_arr[t - 1][tid] < tgt) { }
            }
            __threadfence();
            __syncthreads();

            const unsigned* __restrict__ hp =
                g_hs_bf + (size_t)(t - 1) * BATCH * (HDIM / 2);

            /* stage chunk 0 */
#pragma unroll
            for (int i = 0; i < 8; i++) {
                const int u16 = sq + 4 * i;      /* 16B unit 0..31 */
                cp_async16((float*)&hs0[sb * HSW + u16 * 4],
                           (const float*)&hp[(size_t)sb * 512 + u16 * 4]);
            }
            cp_commit();

            float acc[4][4];
#pragma unroll
            for (int nt = 0; nt < 4; nt++)
#pragma unroll
                for (int v = 0; v < 4; v++) acc[nt][v] = 0.0f;

#pragma unroll 1
            for (int ch = 0; ch < 4; ch++) {
                if (ch < 3) {
                    unsigned* dst = hs0 + ((ch + 1) & 1) * HCHUNK_W;
#pragma unroll
                    for (int i = 0; i < 8; i++) {
                        const int u16 = sq + 4 * i;
                        cp_async16((float*)&dst[sb * HSW + u16 * 4],
                                   (const float*)&hp[(size_t)sb * 512 +
                                                     (ch + 1) * 128 + u16 * 4]);
                    }
                    cp_commit();
                    cp_wait1();
                } else {
                    cp_wait0();
                }
                __syncthreads();

                const unsigned* Ab = hs0 + (ch & 1) * HCHUNK_W
                                     + (mg * 16) * HSW + kg * 64;
                const unsigned* Wb = Ws + ch * 128 + kg * 64;
#pragma unroll
                for (int ks = 0; ks < 8; ks++) {
                    const int colw = ks * 8 + (lane & 3);
                    unsigned af[4];
                    {
                        const unsigned* a = Ab + (lane >> 2) * HSW + colw;
                        af[0] = a[0];
                        af[1] = a[8 * HSW];
                        af[2] = a[4];
                        af[3] = a[8 * HSW + 4];
                    }
#pragma unroll
                    for (int nt = 0; nt < 4; nt++) {
                        const unsigned* b = Wb + (nt * 8 + (lane >> 2)) * WSW + colw;
                        unsigned bf[2];
                        bf[0] = b[0];
                        bf[1] = b[4];
                        mma_bf16(acc[nt], af, bf);
                    }
                }
                __syncthreads();
            }

            {
                float* pg = pre + kg * PRE_SZ;
#pragma unroll
                for (int nt = 0; nt < 4; nt++) {
                    const int m = mg * 16 + (lane >> 2);
                    const int n = nt * 8 + 2 * (lane & 3);
                    *(float2*)&pg[m * PST + n]       = make_float2(acc[nt][0], acc[nt][1]);
                    *(float2*)&pg[(m + 8) * PST + n] = make_float2(acc[nt][2], acc[nt][3]);
                }
            }
        }
        __syncthreads();

        /* gate math: 2 cells per thread */
        {
            float s0[4], s1[4];
            if (t > 0) {
                float4 p00 = *(const float4*)&pre[gb * PST + gu0 * 4];
                float4 p01 = *(const float4*)&pre[PRE_SZ + gb * PST + gu0 * 4];
                float4 p10 = *(const float4*)&pre[gb * PST + gu1 * 4];
                float4 p11 = *(const float4*)&pre[PRE_SZ + gb * PST + gu1 * 4];
                s0[0] = p00.x + p01.x; s0[1] = p00.y + p01.y;
                s0[2] = p00.z + p01.z; s0[3] = p00.w + p01.w;
                s1[0] = p10.x + p11.x; s1[1] = p10.y + p11.y;
                s1[2] = p10.z + p11.z; s1[3] = p10.w + p11.w;
            } else {
#pragma unroll
                for (int g = 0; g < 4; g++) { s0[g] = 0.0f; s1[g] = 0.0f; }
            }
#pragma unroll
            for (int g = 0; g < 4; g++) {
                s0[g] += xp0[g] + bh0[g];
                s1[g] += xp1[g] + bh1[g];
            }
            unsigned short* hb =
                (unsigned short*)g_hs_bf + (size_t)t * BATCH * HDIM +
                (size_t)gb * HDIM + j0;
            float* h32 = g_hs32 + (size_t)t * BATCH * HDIM + (size_t)gb * HDIM + j0;
            {
                float ig = sigmoidf_(s0[0]), fg = sigmoidf_(s0[1]);
                float gg = tanhf(s0[2]),     og = sigmoidf_(s0[3]);
                c0 = fg * c0 + ig * gg;
                float hv = og * tanhf(c0);
                __nv_bfloat16 hb16 = __float2bfloat16(hv);
                hb[gu0]  = reinterpret_cast<unsigned short&>(hb16);
                h32[gu0] = hv;
            }
            {
                float ig = sigmoidf_(s1[0]), fg = sigmoidf_(s1[1]);
                float gg = tanhf(s1[2]),     og = sigmoidf_(s1[3]);
                c1 = fg * c1 + ig * gg;
                float hv = og * tanhf(c1);
                __nv_bfloat16 hb16 = __float2bfloat16(hv);
                hb[gu1]  = reinterpret_cast<unsigned short&>(hb16);
                h32[gu1] = hv;
            }
        }

        /* publish h(t): release fence then per-CTA flag (no atomics) */
        __threadfence();
        __syncthreads();
        if (tid == 0)
            *(volatile unsigned*)&g_arr[t][bid] = tgt;
    }

    /* final ticket barrier, then epoch++ (replay-safe) */
    if (tid == 0) {
        __threadfence();
        unsigned ticket = atomicAdd(&g_bar, 1u);
        unsigned target = (ticket / NBLK_LSTM + 1u) * NBLK_LSTM;
        while (*((volatile unsigned*)&g_bar) < target) { }
    }
    __syncthreads();
    if (bid == 0 && tid == 0) {
        __threadfence();
        *(volatile unsigned*)&g_epoch = epoch + 1u;
    }
}

/* ------------------------------------------------------------------ */
__global__ __launch_bounds__(256)
void logsoftmax_kernel(float* __restrict__ out) {
    __shared__ float red[8];
    const int row = blockIdx.x;
    const int tid = threadIdx.x;
    const float* x = g_logits + (size_t)row * INDIM;
    float v0 = x[tid];
    float v1 = x[tid + 256];

    float m = fmaxf(v0, v1);
#pragma unroll
    for (int o = 16; o; o >>= 1) m = fmaxf(m, __shfl_xor_sync(0xffffffffu, m, o));
    if ((tid & 31) == 0) red[tid >> 5] = m;
    __syncthreads();
    float M = fmaxf(fmaxf(fmaxf(red[0], red[1]), fmaxf(red[2], red[3])),
                    fmaxf(fmaxf(red[4], red[5]), fmaxf(red[6], red[7])));
    __syncthreads();

    float s = expf(v0 - M) + expf(v1 - M);
#pragma unroll
    for (int o = 16; o; o >>= 1) s += __shfl_xor_sync(0xffffffffu, s, o);
    if ((tid & 31) == 0) red[tid >> 5] = s;
    __syncthreads();
    float S = (red[0] + red[1]) + (red[2] + red[3]) +
              (red[4] + red[5]) + (red[6] + red[7]);
    float lse = M + logf(S);

    out[(size_t)row * INDIM + tid]       = v0 - lse;
    out[(size_t)row * INDIM + tid + 256] = v1 - lse;
}

/* ------------------------------------------------------------------ */
extern "C" void kernel_launch(void* const* d_in, const int* in_sizes, int n_in,
                              void* d_out, int out_size) {
    const float* inp  = (const float*)d_in[0];
    const float* img  = (const float*)d_in[1];
    const float* Wxh  = (const float*)d_in[2];
    const float* bxh  = (const float*)d_in[3];
    const float* Whh  = (const float*)d_in[4];
    const float* bhh  = (const float*)d_in[5];
    const float* Wout = (const float*)d_in[6];
    const float* bout = (const float*)d_in[7];
    float* out = (float*)d_out;

    const int gemm_smem = 2 * 2 * 128 * GST * (int)sizeof(float);          /* 73.7 KB */
    const int lstm_smem = (PRE_OFF_W + 2 * PRE_SZ) * (int)sizeof(unsigned);/* ~152 KB */

    cudaFuncSetAttribute(gemm_tf32<INDIM, G4, 0>,
                         cudaFuncAttributeMaxDynamicSharedMemorySize, gemm_smem);
    cudaFuncSetAttribute(gemm_tf32<HDIM, INDIM, 1>,
                         cudaFuncAttributeMaxDynamicSharedMemorySize, gemm_smem);
    cudaFuncSetAttribute(lstm_kernel,
                         cudaFuncAttributeMaxDynamicSharedMemorySize, lstm_smem);

    gemm_tf32<INDIM, G4, 0><<<dim3(G4 / 128, M_TOT / 128), 256, gemm_smem>>>
        (inp, Wxh, bxh, img);
    lstm_kernel<<<NBLK_LSTM, 256, lstm_smem>>>(Whh, bhh);
    gemm_tf32<HDIM, INDIM, 1><<<dim3(INDIM / 128, M_TOT / 128), 256, gemm_smem>>>
        (nullptr, Wout, bout, nullptr);
    logsoftmax_kernel<<<M_TOT, 256>>>(out);
}

// round 15
// speedup vs baseline: 2.5492x; 1.7634x over previous
#include <cuda_runtime.h>
#include <cuda_bf16.h>
#include <math.h>

#define T_LEN 256
#define BATCH 64
#define INDIM 512
#define HDIM  1024
#define M_TOT (T_LEN * BATCH)   /* 16384 */
#define G4    (4 * HDIM)        /* 4096  */
#define NBLK_LSTM 128

/* h chunk geometry: 4 chunks of 256 k; rows padded to 132 words */
#define HSW      132                       /* words per h row      */
#define HCHUNK_W (64 * HSW)                /* 8448 words = 33792 B */
#define HCHUNK_B (HCHUNK_W * 4)

/* ------------------------------------------------------------------ */
__device__ float    g_xproj [M_TOT * G4];
__device__ __align__(256) unsigned g_hs_bf[T_LEN * 4 * HCHUNK_W]; /* bf16 h, chunk-major padded */
__device__ float    g_hs32  [M_TOT * HDIM];                       /* fp32 h for GEMM1 */
__device__ float    g_logits[M_TOT * INDIM];
__device__ unsigned g_arr   [T_LEN][NBLK_LSTM];
__device__ unsigned g_epoch;
__device__ unsigned g_bar;

/* ------------------------------------------------------------------ */
__device__ __forceinline__ float sigmoidf_(float x) {
    return 1.0f / (1.0f + expf(-x));
}
__device__ __forceinline__ void cp_async16(float* smem_dst, const float* gsrc) {
    unsigned sa = (unsigned)__cvta_generic_to_shared(smem_dst);
    asm volatile("cp.async.cg.shared.global [%0], [%1], 16;\n" :: "r"(sa), "l"(gsrc));
}
__device__ __forceinline__ void cp_commit() {
    asm volatile("cp.async.commit_group;\n" ::: "memory");
}
__device__ __forceinline__ void cp_wait0() {
    asm volatile("cp.async.wait_group 0;\n" ::: "memory");
}
__device__ __forceinline__ void cp_wait1() {
    asm volatile("cp.async.wait_group 1;\n" ::: "memory");
}

/* mbarrier + bulk-copy helpers */
__device__ __forceinline__ void mbar_init(unsigned mbar, unsigned cnt) {
    asm volatile("mbarrier.init.shared.b64 [%0], %1;" :: "r"(mbar), "r"(cnt) : "memory");
}
__device__ __forceinline__ void mbar_expect_tx(unsigned mbar, unsigned bytes) {
    asm volatile("mbarrier.arrive.expect_tx.shared.b64 _, [%0], %1;"
                 :: "r"(mbar), "r"(bytes) : "memory");
}
__device__ __forceinline__ void bulk_g2s(unsigned sdst, const void* gsrc,
                                         unsigned bytes, unsigned mbar) {
    asm volatile(
        "cp.async.bulk.shared::cluster.global.mbarrier::complete_tx::bytes "
        "[%0], [%1], %2, [%3];"
        :: "r"(sdst), "l"(gsrc), "r"(bytes), "r"(mbar) : "memory");
}
__device__ __forceinline__ void mbar_wait(unsigned mbar, unsigned parity) {
    asm volatile(
        "{\n\t.reg .pred P;\n\t"
        "WL_%=:\n\t"
        "mbarrier.try_wait.parity.acquire.cta.shared::cta.b64 P, [%0], %1, 0x989680;\n\t"
        "@P bra.uni WD_%=;\n\t"
        "bra.uni WL_%=;\n\t"
        "WD_%=:\n\t}"
        :: "r"(mbar), "r"(parity) : "memory");
}

/* tf32 mma m16n8k8 (fp32 accum) — GEMMs */
__device__ __forceinline__ void mma_tf32(float* c, const unsigned* a,
                                         const unsigned* b) {
    asm volatile(
        "mma.sync.aligned.m16n8k8.row.col.f32.tf32.tf32.f32 "
        "{%0,%1,%2,%3}, {%4,%5,%6,%7}, {%8,%9}, {%0,%1,%2,%3};"
        : "+f"(c[0]), "+f"(c[1]), "+f"(c[2]), "+f"(c[3])
        : "r"(a[0]), "r"(a[1]), "r"(a[2]), "r"(a[3]), "r"(b[0]), "r"(b[1]));
}
/* bf16 mma m16n8k16 (fp32 accum) — recurrence */
__device__ __forceinline__ void mma_bf16(float* c, const unsigned* a,
                                         const unsigned* b) {
    asm volatile(
        "mma.sync.aligned.m16n8k16.row.col.f32.bf16.bf16.f32 "
        "{%0,%1,%2,%3}, {%4,%5,%6,%7}, {%8,%9}, {%0,%1,%2,%3};"
        : "+f"(c[0]), "+f"(c[1]), "+f"(c[2]), "+f"(c[3])
        : "r"(a[0]), "r"(a[1]), "r"(a[2]), "r"(a[3]), "r"(b[0]), "r"(b[1]));
}
__device__ __forceinline__ unsigned fbits(float x) { return __float_as_uint(x); }

/* ------------------------------------------------------------------ */
/* tf32 GEMM (unchanged, proven)                                      */
/* ------------------------------------------------------------------ */
#define GST 36

template <int KDIM, int NDIM, int MODE>
__global__ __launch_bounds__(256, 2)
void gemm_tf32(const float* __restrict__ Aext,
               const float* __restrict__ B,
               const float* __restrict__ bias,
               const float* __restrict__ img) {
    extern __shared__ __align__(16) float sm[];
    const float* __restrict__ Ap = (MODE == 0) ? Aext : g_hs32;
    float* __restrict__       Cp = (MODE == 0) ? g_xproj : g_logits;

    const int bm   = blockIdx.y * 128;
    const int bn   = blockIdx.x * 128;
    const int tid  = threadIdx.x;
    const int lane = tid & 31;
    const int warp = tid >> 5;
    const int wm   = warp & 1;
    const int wn   = warp >> 1;

    float acc[4][4][4];
#pragma unroll
    for (int i = 0; i < 4; i++)
#pragma unroll
        for (int j = 0; j < 4; j++)
#pragma unroll
            for (int v = 0; v < 4; v++) acc[i][j][v] = 0.0f;

    const int NCH = KDIM / 32;

    {
        float* As = sm;
        float* Bs = sm + 128 * GST;
#pragma unroll
        for (int i = 0; i < 4; i++) {
            const int idx = tid + i * 256;
            const int row = idx >> 3, q = idx & 7;
            cp_async16(&As[row * GST + q * 4], Ap + (size_t)(bm + row) * KDIM + q * 4);
            cp_async16(&Bs[row * GST + q * 4], B  + (size_t)(bn + row) * KDIM + q * 4);
        }
        cp_commit();
    }

    for (int ck = 0; ck < NCH; ck++) {
        const int buf = ck & 1;
        if (ck + 1 < NCH) {
            float* As = sm + ((ck + 1) & 1) * (256 * GST);
            float* Bs = As + 128 * GST;
            const int kt = (ck + 1) * 32;
#pragma unroll
            for (int i = 0; i < 4; i++) {
                const int idx = tid + i * 256;
                const int row = idx >> 3, q = idx & 7;
                cp_async16(&As[row * GST + q * 4],
                           Ap + (size_t)(bm + row) * KDIM + kt + q * 4);
                cp_async16(&Bs[row * GST + q * 4],
                           B + (size_t)(bn + row) * KDIM + kt + q * 4);
            }
            cp_commit();
            cp_wait1();
        } else {
            cp_wait0();
        }
        __syncthreads();

        const float* As = sm + buf * (256 * GST) + (wm * 64) * GST;
        const float* Bs = sm + buf * (256 * GST) + 128 * GST + (wn * 32) * GST;
#pragma unroll
        for (int ks = 0; ks < 4; ks++) {
            const int col = ks * 8 + (lane & 3);
            unsigned af[4][4];
#pragma unroll
            for (int mt = 0; mt < 4; mt++) {
                const int row = mt * 16 + (lane >> 2);
                af[mt][0] = fbits(As[row * GST + col]);
                af[mt][1] = fbits(As[(row + 8) * GST + col]);
                af[mt][2] = fbits(As[row * GST + col + 4]);
                af[mt][3] = fbits(As[(row + 8) * GST + col + 4]);
            }
#pragma unroll
            for (int nt = 0; nt < 4; nt++) {
                const int nr = nt * 8 + (lane >> 2);
                unsigned bf[2];
                bf[0] = fbits(Bs[nr * GST + col]);
                bf[1] = fbits(Bs[nr * GST + col + 4]);
#pragma unroll
                for (int mt = 0; mt < 4; mt++)
                    mma_tf32(acc[mt][nt], af[mt], bf);
            }
        }
        __syncthreads();
    }

#pragma unroll
    for (int mt = 0; mt < 4; mt++) {
#pragma unroll
        for (int nt = 0; nt < 4; nt++) {
            const int m = bm + wm * 64 + mt * 16 + (lane >> 2);
            const int n = bn + wn * 32 + nt * 8 + 2 * (lane & 3);
            const float2 bv = *(const float2*)&bias[n];
            float o0 = acc[mt][nt][0] + bv.x;
            float o1 = acc[mt][nt][1] + bv.y;
            float o2 = acc[mt][nt][2] + bv.x;
            float o3 = acc[mt][nt][3] + bv.y;
            if (MODE == 0) {
                if (m < BATCH) {
                    o0 += img[m * HDIM + (n & (HDIM - 1))];
                    o1 += img[m * HDIM + ((n + 1) & (HDIM - 1))];
                }
                if (m + 8 < BATCH) {
                    o2 += img[(m + 8) * HDIM + (n & (HDIM - 1))];
                    o3 += img[(m + 8) * HDIM + ((n + 1) & (HDIM - 1))];
                }
            }
            *(float2*)(Cp + (size_t)m * NDIM + n)       = make_float2(o0, o1);
            *(float2*)(Cp + (size_t)(m + 8) * NDIM + n) = make_float2(o2, o3);
        }
    }
}

/* ------------------------------------------------------------------ */
/* Persistent LSTM — bf16 mma + cp.async.bulk chunk staging.          */
/* smem (words): Ws[0,16512) | hs 2x8448 [16512,33408) |              */
/*               pre 2x2304 fp32 [33408,38016) | 2 mbars [38016,38020)*/
/* ------------------------------------------------------------------ */
#define WSW 516
#define PST 36
#define W_WORDS   (32 * WSW)                    /* 16512 */
#define HS_OFF_W  (W_WORDS)
#define PRE_OFF_W (HS_OFF_W + 2 * HCHUNK_W)     /* 33408 */
#define PRE_SZ    (64 * PST)
#define MBAR_OFF_W (PRE_OFF_W + 2 * PRE_SZ)     /* 38016 */
#define LSTM_SMEM_W (MBAR_OFF_W + 8)

__global__ __launch_bounds__(256, 1)
void lstm_kernel(const float* __restrict__ Whh,
                 const float* __restrict__ bhh) {
    extern __shared__ __align__(16) unsigned smu[];
    unsigned* Ws  = smu;
    unsigned* hs0 = smu + HS_OFF_W;
    float*    pre = (float*)(smu + PRE_OFF_W);

    const unsigned smem_base = (unsigned)__cvta_generic_to_shared(smu);
    const unsigned mb[2] = { smem_base + MBAR_OFF_W * 4u,
                             smem_base + MBAR_OFF_W * 4u + 8u };
    const unsigned hs_sa  = smem_base + HS_OFF_W * 4u;

    const int tid  = threadIdx.x;
    const int lane = tid & 31;
    const int warp = tid >> 5;
    const int mg   = warp & 3;     /* 16-batch slice  */
    const int kg   = warp >> 2;    /* k half          */
    const int j0   = blockIdx.x * 8;
    const int bid  = blockIdx.x;
    const int chown = bid >> 5;    /* chunk this CTA's units live in */

    const unsigned epoch = *(volatile unsigned*)&g_epoch;
    const unsigned tgt   = epoch + 1u;

    const int gb  = tid >> 2;
    const int gu0 = tid & 3;
    const int gu1 = gu0 + 4;

    /* stage Whh -> bf16 smem (once): Ws[r][k], r = u*4+g */
    for (int idx = tid; idx < 32 * 256; idx += 256) {
        const int r = idx & 31, k4 = idx >> 5;
        const int u = r >> 2, g = r & 3;
        float4 w = *(const float4*)&Whh[(size_t)(g * HDIM + j0 + u) * HDIM + k4 * 4];
        __nv_bfloat162 lo = __floats2bfloat162_rn(w.x, w.y);
        __nv_bfloat162 hi = __floats2bfloat162_rn(w.z, w.w);
        Ws[r * WSW + k4 * 2]     = reinterpret_cast<unsigned&>(lo);
        Ws[r * WSW + k4 * 2 + 1] = reinterpret_cast<unsigned&>(hi);
    }
    if (tid == 0) {
        mbar_init(mb[0], 1);
        mbar_init(mb[1], 1);
    }
    asm volatile("fence.proxy.async.shared::cta;" ::: "memory");

    float bh0[4], bh1[4];
#pragma unroll
    for (int g = 0; g < 4; g++) {
        bh0[g] = bhh[g * HDIM + j0 + gu0];
        bh1[g] = bhh[g * HDIM + j0 + gu1];
    }
    float c0 = 0.0f, c1 = 0.0f;
    int ph[2] = {0, 0};
    __syncthreads();

    for (int t = 0; t < T_LEN; t++) {
        /* xproj prefetch (overlaps the flag wait) */
        float xp0[4], xp1[4];
        {
            const float* xb = g_xproj + (size_t)t * BATCH * G4 + (size_t)gb * G4 + j0;
#pragma unroll
            for (int g = 0; g < 4; g++) {
                xp0[g] = __ldg(xb + g * HDIM + gu0);
                xp1[g] = __ldg(xb + g * HDIM + gu1);
            }
        }

        if (t > 0) {
            /* all-poll-all barrier: thread i<128 watches CTA i's flag */
            if (tid < NBLK_LSTM) {
                while (*(volatile unsigned*)&g_arr[t - 1][tid] < tgt) { }
            }
            __threadfence();
            __syncthreads();

            const char* __restrict__ hp =
                (const char*)g_hs_bf + (size_t)(t - 1) * 4 * HCHUNK_B;

            /* bulk-stage chunk 0 -> buf 0 */
            if (tid == 0) {
                mbar_expect_tx(mb[0], HCHUNK_B);
                bulk_g2s(hs_sa, hp, HCHUNK_B, mb[0]);
            }

            float acc[4][4];
#pragma unroll
            for (int nt = 0; nt < 4; nt++)
#pragma unroll
                for (int v = 0; v < 4; v++) acc[nt][v] = 0.0f;

#pragma unroll 1
            for (int ch = 0; ch < 4; ch++) {
                const int buf = ch & 1;
                if (ch < 3 && tid == 0) {
                    const int nb = (ch + 1) & 1;
                    mbar_expect_tx(mb[nb], HCHUNK_B);
                    bulk_g2s(hs_sa + nb * HCHUNK_B,
                             hp + (size_t)(ch + 1) * HCHUNK_B, HCHUNK_B, mb[nb]);
                }
                mbar_wait(mb[buf], ph[buf]);
                ph[buf] ^= 1;

                const unsigned* Ab = hs0 + buf * HCHUNK_W
                                     + (mg * 16) * HSW + kg * 64;
                const unsigned* Wb = Ws + ch * 128 + kg * 64;
#pragma unroll
                for (int ks = 0; ks < 8; ks++) {
                    const int colw = ks * 8 + (lane & 3);
                    unsigned af[4];
                    {
                        const unsigned* a = Ab + (lane >> 2) * HSW + colw;
                        af[0] = a[0];
                        af[1] = a[8 * HSW];
                        af[2] = a[4];
                        af[3] = a[8 * HSW + 4];
                    }
#pragma unroll
                    for (int nt = 0; nt < 4; nt++) {
                        const unsigned* b = Wb + (nt * 8 + (lane >> 2)) * WSW + colw;
                        unsigned bf[2];
                        bf[0] = b[0];
                        bf[1] = b[4];
                        mma_bf16(acc[nt], af, bf);
                    }
                }
                __syncthreads();   /* buffer fully consumed before reuse */
            }

            {
                float* pg = pre + kg * PRE_SZ;
#pragma unroll
                for (int nt = 0; nt < 4; nt++) {
                    const int m = mg * 16 + (lane >> 2);
                    const int n = nt * 8 + 2 * (lane & 3);
                    *(float2*)&pg[m * PST + n]       = make_float2(acc[nt][0], acc[nt][1]);
                    *(float2*)&pg[(m + 8) * PST + n] = make_float2(acc[nt][2], acc[nt][3]);
                }
            }
        }
        __syncthreads();

        /* gate math: 2 cells per thread */
        {
            float s0[4], s1[4];
            if (t > 0) {
                float4 p00 = *(const float4*)&pre[gb * PST + gu0 * 4];
                float4 p01 = *(const float4*)&pre[PRE_SZ + gb * PST + gu0 * 4];
                float4 p10 = *(const float4*)&pre[gb * PST + gu1 * 4];
                float4 p11 = *(const float4*)&pre[PRE_SZ + gb * PST + gu1 * 4];
                s0[0] = p00.x + p01.x; s0[1] = p00.y + p01.y;
                s0[2] = p00.z + p01.z; s0[3] = p00.w + p01.w;
                s1[0] = p10.x + p11.x; s1[1] = p10.y + p11.y;
                s1[2] = p10.z + p11.z; s1[3] = p10.w + p11.w;
            } else {
#pragma unroll
                for (int g = 0; g < 4; g++) { s0[g] = 0.0f; s1[g] = 0.0f; }
            }
#pragma unroll
            for (int g = 0; g < 4; g++) {
                s0[g] += xp0[g] + bh0[g];
                s1[g] += xp1[g] + bh1[g];
            }
            /* bf16 h: chunk-major padded layout [t][ch][b][264 bf16] */
            unsigned short* hb =
                (unsigned short*)g_hs_bf +
                ((size_t)(t * 4 + chown) * 64 + gb) * (HSW * 2) + (j0 & 255);
            float* h32 = g_hs32 + (size_t)t * BATCH * HDIM + (size_t)gb * HDIM + j0;
            {
                float ig = sigmoidf_(s0[0]), fg = sigmoidf_(s0[1]);
                float gg = tanhf(s0[2]),     og = sigmoidf_(s0[3]);
                c0 = fg * c0 + ig * gg;
                float hv = og * tanhf(c0);
                __nv_bfloat16 hb16 = __float2bfloat16(hv);
                hb[gu0]  = reinterpret_cast<unsigned short&>(hb16);
                h32[gu0] = hv;
            }
            {
                float ig = sigmoidf_(s1[0]), fg = sigmoidf_(s1[1]);
                float gg = tanhf(s1[2]),     og = sigmoidf_(s1[3]);
                c1 = fg * c1 + ig * gg;
                float hv = og * tanhf(c1);
                __nv_bfloat16 hb16 = __float2bfloat16(hv);
                hb[gu1]  = reinterpret_cast<unsigned short&>(hb16);
                h32[gu1] = hv;
            }
        }

        /* publish h(t): release fence then per-CTA flag */
        __threadfence();
        __syncthreads();
        if (tid == 0)
            *(volatile unsigned*)&g_arr[t][bid] = tgt;
    }

    /* final ticket barrier, then epoch++ (replay-safe) */
    if (tid == 0) {
        __threadfence();
        unsigned ticket = atomicAdd(&g_bar, 1u);
        unsigned target = (ticket / NBLK_LSTM + 1u) * NBLK_LSTM;
        while (*((volatile unsigned*)&g_bar) < target) { }
    }
    __syncthreads();
    if (bid == 0 && tid == 0) {
        __threadfence();
        *(volatile unsigned*)&g_epoch = epoch + 1u;
    }
}

/* ------------------------------------------------------------------ */
__global__ __launch_bounds__(256)
void logsoftmax_kernel(float* __restrict__ out) {
    __shared__ float red[8];
    const int row = blockIdx.x;
    const int tid = threadIdx.x;
    const float* x = g_logits + (size_t)row * INDIM;
    float v0 = x[tid];
    float v1 = x[tid + 256];

    float m = fmaxf(v0, v1);
#pragma unroll
    for (int o = 16; o; o >>= 1) m = fmaxf(m, __shfl_xor_sync(0xffffffffu, m, o));
    if ((tid & 31) == 0) red[tid >> 5] = m;
    __syncthreads();
    float M = fmaxf(fmaxf(fmaxf(red[0], red[1]), fmaxf(red[2], red[3])),
                    fmaxf(fmaxf(red[4], red[5]), fmaxf(red[6], red[7])));
    __syncthreads();

    float s = expf(v0 - M) + expf(v1 - M);
#pragma unroll
    for (int o = 16; o; o >>= 1) s += __shfl_xor_sync(0xffffffffu, s, o);
    if ((tid & 31) == 0) red[tid >> 5] = s;
    __syncthreads();
    float S = (red[0] + red[1]) + (red[2] + red[3]) +
              (red[4] + red[5]) + (red[6] + red[7]);
    float lse = M + logf(S);

    out[(size_t)row * INDIM + tid]       = v0 - lse;
    out[(size_t)row * INDIM + tid + 256] = v1 - lse;
}

/* ------------------------------------------------------------------ */
extern "C" void kernel_launch(void* const* d_in, const int* in_sizes, int n_in,
                              void* d_out, int out_size) {
    const float* inp  = (const float*)d_in[0];
    const float* img  = (const float*)d_in[1];
    const float* Wxh  = (const float*)d_in[2];
    const float* bxh  = (const float*)d_in[3];
    const float* Whh  = (const float*)d_in[4];
    const float* bhh  = (const float*)d_in[5];
    const float* Wout = (const float*)d_in[6];
    const float* bout = (const float*)d_in[7];
    float* out = (float*)d_out;

    const int gemm_smem = 2 * 2 * 128 * GST * (int)sizeof(float);   /* 73.7 KB */
    const int lstm_smem = LSTM_SMEM_W * (int)sizeof(unsigned);      /* ~152 KB */

    cudaFuncSetAttribute(gemm_tf32<INDIM, G4, 0>,
                         cudaFuncAttributeMaxDynamicSharedMemorySize, gemm_smem);
    cudaFuncSetAttribute(gemm_tf32<HDIM, INDIM, 1>,
                         cudaFuncAttributeMaxDynamicSharedMemorySize, gemm_smem);
    cudaFuncSetAttribute(lstm_kernel,
                         cudaFuncAttributeMaxDynamicSharedMemorySize, lstm_smem);

    gemm_tf32<INDIM, G4, 0><<<dim3(G4 / 128, M_TOT / 128), 256, gemm_smem>>>
        (inp, Wxh, bxh, img);
    lstm_kernel<<<NBLK_LSTM, 256, lstm_smem>>>(Whh, bhh);
    gemm_tf32<HDIM, INDIM, 1><<<dim3(INDIM / 128, M_TOT / 128), 256, gemm_smem>>>
        (nullptr, Wout, bout, nullptr);
    logsoftmax_kernel<<<M_TOT, 256>>>(out);
}